// round 13
// baseline (speedup 1.0000x reference)
#include <cuda_runtime.h>
#include <cuda_bf16.h>
#include <cstdint>

// Problem constants
#define NTOK   8192
#define DMODEL 4096
#define DSAE   16384
#define KSP    64

// band must exceed 2x the max |pre_computed - pre_true| (int8-path: ~3.8e-4 max)
#define BAND_EPS 8e-4f

// d_out layout: [recon (NTOK*DMODEL) | sparse (NTOK*DSAE) | pre (NTOK*DSAE)]

// ---------------- scratch (__device__ globals) ----------------
__device__ float g_WdecT[(size_t)DSAE * DMODEL];   // 256 MB transposed decoder weights
__device__ int   g_topidx[(size_t)NTOK * KSP];
__device__ float g_topval[(size_t)NTOK * KSP];
__device__ float g_vT[NTOK];
__device__ int   g_flag[NTOK];
// int8 two-digit fixed-point operands for IMMA encoder
__device__ int8_t g_X1[(size_t)NTOK * DMODEL];     // 32 MB
__device__ int8_t g_X2[(size_t)NTOK * DMODEL];     // 32 MB
__device__ int8_t g_W1[(size_t)DSAE * DMODEL];     // 64 MB
__device__ int8_t g_W2[(size_t)DSAE * DMODEL];     // 64 MB
__device__ float  g_sxa[NTOK];                     // per-row scale of x
__device__ float  g_sxw[DSAE];                     // per-row scale of W_enc

// ---------------- baseline-PTX helpers (sm_80-level only; NO _a features) -----
__device__ __forceinline__ uint32_t smem_to_u32(const void* p) {
    uint32_t a;
    asm("{ .reg .u64 t; cvta.to.shared.u64 t, %1; cvt.u32.u64 %0, t; }"
        : "=r"(a) : "l"(p));
    return a;
}
__device__ __forceinline__ void cp_async16(uint32_t saddr, const void* gaddr) {
    asm volatile("cp.async.cg.shared.global [%0], [%1], 16;" :: "r"(saddr), "l"(gaddr));
}
#define CP_COMMIT() asm volatile("cp.async.commit_group;" ::: "memory")
template <int N>
__device__ __forceinline__ void cp_wait_group() {
    asm volatile("cp.async.wait_group %0;" :: "n"(N) : "memory");
}

// mma.sync m16n8k32 row.col s8 -> s32 (PTX ISA 7.0, baseline sm_80)
__device__ __forceinline__ void imma16832(int* d, const uint32_t* a, const uint32_t* b) {
    asm volatile(
        "mma.sync.aligned.m16n8k32.row.col.s32.s8.s8.s32 "
        "{%0,%1,%2,%3}, {%4,%5,%6,%7}, {%8,%9}, {%0,%1,%2,%3};"
        : "+r"(d[0]), "+r"(d[1]), "+r"(d[2]), "+r"(d[3])
        : "r"(a[0]), "r"(a[1]), "r"(a[2]), "r"(a[3]), "r"(b[0]), "r"(b[1]));
}

// =====================================================================
// Kernel 0: per-row two-digit int8 quantization.
//   s = max|row| / 16256;  v ~= s * (128*X1 + X2),  |residual| <= s/2
// =====================================================================
__global__ __launch_bounds__(256)
void quant_rows(const float* __restrict__ src, int8_t* __restrict__ d1,
                int8_t* __restrict__ d2, float* __restrict__ scale, int ncols)
{
    __shared__ float red[256];
    const int row = blockIdx.x;
    const int tid = threadIdx.x;
    const float* s = src + (size_t)row * ncols;

    float mx = 0.0f;
    for (int i = tid; i < ncols; i += 256) mx = fmaxf(mx, fabsf(s[i]));
    red[tid] = mx;
    __syncthreads();
    for (int o = 128; o > 0; o >>= 1) {
        if (tid < o) red[tid] = fmaxf(red[tid], red[tid + o]);
        __syncthreads();
    }
    const float sx  = fmaxf(red[0], 1e-30f) * (1.0f / 16256.0f);
    const float inv = 1.0f / sx;
    if (tid == 0) scale[row] = sx;

    for (int i = tid; i < ncols; i += 256) {
        float v = s[i];
        int x1 = __float2int_rn(v * inv * (1.0f / 128.0f));
        x1 = max(-127, min(127, x1));
        float r = v - sx * 128.0f * (float)x1;
        int x2 = __float2int_rn(r * inv);
        x2 = max(-127, min(127, x2));
        d1[(size_t)row * ncols + i] = (int8_t)x1;
        d2[(size_t)row * ncols + i] = (int8_t)x2;
    }
}

// =====================================================================
// Kernel 1: IMMA encoder GEMM (int8 two-digit):
//   pre[m,f] = sxa[m]*sxw[f]*(16384*S11 + 128*S12) + bias[f]
//   S11 = X1·W1^T,  S12 = X1·W2^T + X2·W1^T   (exact int32 accumulation)
// CTA 128x128, BK=64 (bytes), 3-stage cp.async, 256 threads,
// warp tile 32x64, m16n8k32 -> HALF the MMA instructions of bf16x3.
// Row stride 80B: bank = 20g+tg (+4h) covers all 32 banks (conflict-free).
// =====================================================================
#define IB_BM 128
#define IB_BN 128
#define IB_BK 64
#define IB_RS 80                         // 64B data + 16B pad
#define IB_MAT (128 * IB_RS)             // 10240 B per digit matrix
#define IB_STAGE (4 * IB_MAT)            // X1,X2,W1,W2 = 40960 B
#define IB_NSTAGE 3
#define IB_SMEM (IB_NSTAGE * IB_STAGE)   // 122880 B
#define OFF_X1 0
#define OFF_X2 IB_MAT
#define OFF_W1 (2 * IB_MAT)
#define OFF_W2 (3 * IB_MAT)

__global__ __launch_bounds__(256, 1)
void enc_imma(const float* __restrict__ bias, float* __restrict__ C)
{
    extern __shared__ char smem[];
    const int tid  = threadIdx.x;
    const int wid  = tid >> 5;
    const int lane = tid & 31;

    // rasterize: groups of 8 M-tiles x all 128 N-tiles
    const int t  = blockIdx.x;
    const int g  = t >> 10;             // /(8*128)
    const int r  = t & 1023;
    const int mt = (g << 3) + (r & 7);
    const int nt = r >> 3;
    const int m0 = mt * IB_BM;
    const int n0 = nt * IB_BN;

    const int warp_m = (wid >> 1) * 32;   // 0,32,64,96
    const int warp_n = (wid & 1) * 64;    // 0,64

    int s11[2][8][4], s12[2][8][4];
#pragma unroll
    for (int i = 0; i < 2; i++)
#pragma unroll
        for (int j = 0; j < 8; j++)
#pragma unroll
            for (int q = 0; q < 4; q++) { s11[i][j][q] = 0; s12[i][j][q] = 0; }

    const uint32_t sb = smem_to_u32(smem);
    const int NCH = DMODEL / IB_BK;      // 64

    // ---- per-thread loader plan: 8 x 16B chunks per stage (2048 total) ----
    uint32_t soff[8];
    const char* gptr[8];
    {
        const char* gb[4] = {
            (const char*)g_X1 + (size_t)m0 * DMODEL,
            (const char*)g_X2 + (size_t)m0 * DMODEL,
            (const char*)g_W1 + (size_t)n0 * DMODEL,
            (const char*)g_W2 + (size_t)n0 * DMODEL
        };
#pragma unroll
        for (int i = 0; i < 8; i++) {
            int c   = tid + i * 256;
            int mat = c >> 9;            // 0..3
            int rem = c & 511;
            int row = rem >> 2;          // 0..127
            int c16 = rem & 3;           // 0..3
            soff[i] = mat * IB_MAT + row * IB_RS + c16 * 16;
            gptr[i] = gb[mat] + (size_t)row * DMODEL + c16 * 16;
        }
    }

    auto load_stage = [&](int ch, int s) {
        const uint32_t stg = sb + s * IB_STAGE;
        const size_t kadv = (size_t)ch * IB_BK;   // 64 bytes per chunk
#pragma unroll
        for (int i = 0; i < 8; i++)
            cp_async16(stg + soff[i], gptr[i] + kadv);
        CP_COMMIT();
    };

    load_stage(0, 0);
    load_stage(1, 1);

    const int gg = lane >> 2;
    const int tg = lane & 3;

    for (int ch = 0; ch < NCH; ch++) {
        if (ch + 1 < NCH) cp_wait_group<1>();
        else              cp_wait_group<0>();
        __syncthreads();

        if (ch + 2 < NCH) load_stage(ch + 2, (ch + 2) % 3);

        const char* stg = smem + (ch % 3) * IB_STAGE;

#pragma unroll
        for (int ks = 0; ks < 2; ks++) {
            const int kb = ks * 32;      // 32 int8 = 32B per k-step
            uint32_t a1[2][4], a2[2][4], b1[8][2], b2[8][2];
#pragma unroll
            for (int i = 0; i < 2; i++) {
                const char* p1 = stg + OFF_X1 +
                                 (warp_m + i * 16 + gg) * IB_RS + kb + tg * 4;
                a1[i][0] = *(const uint32_t*)p1;
                a1[i][1] = *(const uint32_t*)(p1 + 8 * IB_RS);
                a1[i][2] = *(const uint32_t*)(p1 + 16);
                a1[i][3] = *(const uint32_t*)(p1 + 8 * IB_RS + 16);
                const char* p2 = p1 + (OFF_X2 - OFF_X1);
                a2[i][0] = *(const uint32_t*)p2;
                a2[i][1] = *(const uint32_t*)(p2 + 8 * IB_RS);
                a2[i][2] = *(const uint32_t*)(p2 + 16);
                a2[i][3] = *(const uint32_t*)(p2 + 8 * IB_RS + 16);
            }
#pragma unroll
            for (int j = 0; j < 8; j++) {
                const char* p1 = stg + OFF_W1 +
                                 (warp_n + j * 8 + gg) * IB_RS + kb + tg * 4;
                b1[j][0] = *(const uint32_t*)p1;
                b1[j][1] = *(const uint32_t*)(p1 + 16);
                const char* p2 = p1 + (OFF_W2 - OFF_W1);
                b2[j][0] = *(const uint32_t*)p2;
                b2[j][1] = *(const uint32_t*)(p2 + 16);
            }
            // pass 1: S11 += X1*W1
#pragma unroll
            for (int j = 0; j < 8; j++)
#pragma unroll
                for (int i = 0; i < 2; i++)
                    imma16832(s11[i][j], a1[i], b1[j]);
            // pass 2: S12 += X1*W2
#pragma unroll
            for (int j = 0; j < 8; j++)
#pragma unroll
                for (int i = 0; i < 2; i++)
                    imma16832(s12[i][j], a1[i], b2[j]);
            // pass 3: S12 += X2*W1
#pragma unroll
            for (int j = 0; j < 8; j++)
#pragma unroll
                for (int i = 0; i < 2; i++)
                    imma16832(s12[i][j], a2[i], b1[j]);
        }
    }

    // ---- epilogue: scale combine + bias + store ----
#pragma unroll
    for (int i = 0; i < 2; i++) {
        const int row0 = m0 + warp_m + i * 16 + gg;
        const float sx0 = g_sxa[row0];
        const float sx8 = g_sxa[row0 + 8];
#pragma unroll
        for (int j = 0; j < 8; j++) {
            const int col = n0 + warp_n + j * 8 + tg * 2;
            const float sw0 = g_sxw[col];
            const float sw1 = g_sxw[col + 1];
            const float b0 = bias[col];
            const float b1 = bias[col + 1];
            float v00 = sx0 * sw0 * fmaf(16384.f, (float)s11[i][j][0], 128.f * (float)s12[i][j][0]) + b0;
            float v01 = sx0 * sw1 * fmaf(16384.f, (float)s11[i][j][1], 128.f * (float)s12[i][j][1]) + b1;
            float v10 = sx8 * sw0 * fmaf(16384.f, (float)s11[i][j][2], 128.f * (float)s12[i][j][2]) + b0;
            float v11 = sx8 * sw1 * fmaf(16384.f, (float)s11[i][j][3], 128.f * (float)s12[i][j][3]) + b1;
            float* p0 = C + (size_t)row0 * DSAE + col;
            float* p1 = C + (size_t)(row0 + 8) * DSAE + col;
            *(float2*)p0 = make_float2(v00, v01);
            *(float2*)p1 = make_float2(v10, v11);
        }
    }
}

// =====================================================================
// Kernel 2: transpose W_dec (DMODEL x DSAE) -> g_WdecT (DSAE x DMODEL)
// =====================================================================
__global__ __launch_bounds__(256)
void wdec_transpose(const float* __restrict__ W)
{
    __shared__ float s[32][33];
    const int f0 = blockIdx.x * 32;
    const int d0 = blockIdx.y * 32;
    const int tx = threadIdx.x;
    const int ty = threadIdx.y;
#pragma unroll
    for (int j = 0; j < 32; j += 8)
        s[ty + j][tx] = W[(size_t)(d0 + ty + j) * DSAE + f0 + tx];
    __syncthreads();
#pragma unroll
    for (int j = 0; j < 32; j += 8)
        g_WdecT[(size_t)(f0 + ty + j) * DMODEL + d0 + tx] = s[tx][ty + j];
}

// =====================================================================
// Kernel 3: per-token top-64 radix select (exact on our computed values,
// lowest-index tie-break) + ambiguity flagging
// =====================================================================
__device__ __forceinline__ unsigned int fkey(float x) {
    unsigned int u = __float_as_uint(x);
    unsigned int m = ((unsigned int)((int)u >> 31)) | 0x80000000u;
    return u ^ m;
}
__device__ __forceinline__ float keyval(unsigned int k) {
    unsigned int u = (k & 0x80000000u) ? (k ^ 0x80000000u) : ~k;
    return __uint_as_float(u);
}

__global__ __launch_bounds__(256)
void topk_select(const float* __restrict__ pre, float* __restrict__ sparse)
{
    extern __shared__ float srow[];
    __shared__ unsigned int hist[8][256];
    __shared__ unsigned int bitmap[DSAE / 32];
    __shared__ int s_gt[256], s_eq[256], s_base[256], s_ebase[256];
    __shared__ unsigned int sh_pfx;
    __shared__ int sh_need;
    __shared__ int s_flag;

    const int token = blockIdx.x;
    const int tid = threadIdx.x;
    const int wid = tid >> 5;
    const float* prow = pre + (size_t)token * DSAE;

    for (int i = tid; i < DSAE; i += 256) srow[i] = prow[i];
    __syncthreads();

    unsigned int pfx = 0;
    int need = KSP;
    for (int b = 3; b >= 0; --b) {
        for (int i = tid; i < 8 * 256; i += 256) ((unsigned int*)hist)[i] = 0;
        __syncthreads();
        const int sh = b * 8;
        for (int i = tid; i < DSAE; i += 256) {
            unsigned int k = fkey(srow[i]);
            bool m = (b == 3) || ((k >> (sh + 8)) == pfx);
            if (m) atomicAdd(&hist[wid][(k >> sh) & 255], 1u);
        }
        __syncthreads();
        if (tid < 256) {
            unsigned int s = 0;
#pragma unroll
            for (int w = 0; w < 8; w++) s += hist[w][tid];
            hist[0][tid] = s;
        }
        __syncthreads();
        if (tid == 0) {
            int cum = 0, v = 255;
            for (; v > 0; --v) {
                int c = (int)hist[0][v];
                if (cum + c >= need) break;
                cum += c;
            }
            sh_pfx = (pfx << 8) | (unsigned int)v;
            sh_need = need - cum;
        }
        __syncthreads();
        pfx = sh_pfx;
        need = sh_need;
        __syncthreads();
    }
    const unsigned int T = pfx;
    const int r = need;
    const float vT = keyval(T);

    const int seg = tid * 64;
    {
        int ngt = 0, neq = 0;
#pragma unroll 4
        for (int ii = 0; ii < 64; ii++) {
            unsigned int k = fkey(srow[seg + ii]);
            ngt += (k > T);
            neq += (k == T);
        }
        s_gt[tid] = ngt;
        s_eq[tid] = neq;
    }
    if (tid == 0) s_flag = 0;
    __syncthreads();
    if (tid == 0) {
        int eacc = 0, sacc = 0;
        for (int q = 0; q < 256; q++) {
            s_ebase[q] = eacc;
            int etake = r - eacc;
            if (etake < 0) etake = 0;
            if (etake > s_eq[q]) etake = s_eq[q];
            s_base[q] = sacc;
            sacc += s_gt[q] + etake;
            eacc += s_eq[q];
        }
    }
    __syncthreads();

    {
        unsigned int bits0 = 0, bits1 = 0;
        int p = s_base[tid];
        int e = s_ebase[tid];
        int*   oidx = g_topidx + (size_t)token * KSP;
        float* oval = g_topval + (size_t)token * KSP;
        for (int ii = 0; ii < 64; ii++) {
            int i = seg + ii;
            float x = srow[i];
            unsigned int k = fkey(x);
            bool gt = (k > T);
            bool eq = (k == T);
            bool take = gt || (eq && e < r);
            if (eq) e++;
            if (take) {
                oidx[p] = i;
                oval[p] = x;
                if (ii < 32) bits0 |= (1u << ii);
                else         bits1 |= (1u << (ii - 32));
                p++;
            }
        }
        bitmap[tid * 2]     = bits0;
        bitmap[tid * 2 + 1] = bits1;
    }
    __syncthreads();

    float* srow_out = sparse + (size_t)token * DSAE;
    for (int i = tid; i < DSAE; i += 256) {
        bool sel = (bitmap[i >> 5] >> (i & 31)) & 1u;
        float v = srow[i];
        srow_out[i] = sel ? v : 0.0f;
        if (!sel && fabsf(v - vT) <= BAND_EPS) s_flag = 1;
    }
    __syncthreads();
    if (tid == 0) {
        g_vT[token] = vT;
        g_flag[token] = s_flag;
    }
}

// =====================================================================
// Kernel 3b: exact fp64 boundary refinement for flagged tokens
// =====================================================================
__global__ __launch_bounds__(256)
void refine(const float* __restrict__ pre,
            const float* __restrict__ x,
            const float* __restrict__ Wenc,
            float* __restrict__ sparse)
{
    extern __shared__ float srow[];
    __shared__ int    s_band[64];
    __shared__ float  s_ef[64];
    __shared__ double s_red[256];
    __shared__ unsigned int bm[DSAE / 32];
    __shared__ int s_cnt[256], s_base[256];
    __shared__ int s_chosen[64];
    __shared__ int s_nin, s_c, s_nch;

    const int token = blockIdx.x;
    if (!g_flag[token]) return;

    const int tid = threadIdx.x;
    const float vT = g_vT[token];
    const float* prow = pre + (size_t)token * DSAE;

    for (int i = tid; i < DSAE; i += 256) srow[i] = prow[i];
    if (tid == 0) { s_nin = 0; s_c = 0; }
    __syncthreads();

    int nin_local = 0;
    for (int i = tid; i < DSAE; i += 256) {
        float v = srow[i];
        if (v > vT + BAND_EPS) {
            nin_local++;
        } else if (fabsf(v - vT) <= BAND_EPS) {
            int p = atomicAdd(&s_c, 1);
            if (p < 64) s_band[p] = i;
        }
    }
    atomicAdd(&s_nin, nin_local);
    __syncthreads();

    const int c = min(s_c, 64);
    const int need = KSP - s_nin;

    if (tid == 0) {
        for (int a = 1; a < c; a++) {
            int key = s_band[a], b = a - 1;
            for (; b >= 0 && s_band[b] > key; b--) s_band[b + 1] = s_band[b];
            s_band[b + 1] = key;
        }
    }
    __syncthreads();

    const float* xr = x + (size_t)token * DMODEL;
    for (int j = 0; j < c; j++) {
        const float* wr = Wenc + (size_t)s_band[j] * DMODEL;
        double p = 0.0;
        for (int d = tid; d < DMODEL; d += 256)
            p += (double)xr[d] * (double)wr[d];
        s_red[tid] = p;
        __syncthreads();
        for (int off = 128; off > 0; off >>= 1) {
            if (tid < off) s_red[tid] += s_red[tid + off];
            __syncthreads();
        }
        if (tid == 0) s_ef[j] = (float)s_red[0];
        __syncthreads();
    }

    if (tid == 0) {
        bool used[64];
        for (int j = 0; j < c; j++) used[j] = false;
        int nc = 0;
        for (int t = 0; t < need && t < c; t++) {
            int best = -1;
            for (int j = 0; j < c; j++)
                if (!used[j] && (best < 0 || s_ef[j] > s_ef[best])) best = j;
            used[best] = true;
            s_chosen[nc++] = s_band[best];
        }
        s_nch = nc;
    }
    __syncthreads();

    {
        int seg = tid * 64;
        unsigned int b0 = 0, b1 = 0;
        for (int ii = 0; ii < 64; ii++) {
            float v = srow[seg + ii];
            if (v > vT + BAND_EPS) {
                if (ii < 32) b0 |= (1u << ii);
                else         b1 |= (1u << (ii - 32));
            }
        }
        bm[tid * 2]     = b0;
        bm[tid * 2 + 1] = b1;
    }
    __syncthreads();
    if (tid == 0)
        for (int t = 0; t < s_nch; t++) {
            int i = s_chosen[t];
            bm[i >> 5] |= (1u << (i & 31));
        }
    __syncthreads();

    s_cnt[tid] = __popc(bm[tid * 2]) + __popc(bm[tid * 2 + 1]);
    __syncthreads();
    if (tid == 0) {
        int acc = 0;
        for (int q = 0; q < 256; q++) { s_base[q] = acc; acc += s_cnt[q]; }
    }
    __syncthreads();

    float* srow_out = sparse + (size_t)token * DSAE;
    int*   oidx = g_topidx + (size_t)token * KSP;
    float* oval = g_topval + (size_t)token * KSP;
    {
        int seg = tid * 64;
        int p = s_base[tid];
        for (int ii = 0; ii < 64; ii++) {
            int i = seg + ii;
            bool sel = (bm[i >> 5] >> (i & 31)) & 1u;
            srow_out[i] = sel ? srow[i] : 0.0f;
            if (sel) { oidx[p] = i; oval[p] = srow[i]; p++; }
        }
    }
}

// =====================================================================
// Kernel 4: sparse decoder
// =====================================================================
__global__ __launch_bounds__(256)
void sparse_decode(const float* __restrict__ bdec,
                   float* __restrict__ recon)
{
    const int token = blockIdx.x;
    const int chunk = blockIdx.y * 1024;
    const int t = threadIdx.x;

    __shared__ int   fi[KSP];
    __shared__ float fv[KSP];
    if (t < KSP) {
        fi[t] = g_topidx[(size_t)token * KSP + t];
        fv[t] = g_topval[(size_t)token * KSP + t];
    }
    __syncthreads();

    float a0 = bdec[chunk + t];
    float a1 = bdec[chunk + 256 + t];
    float a2 = bdec[chunk + 512 + t];
    float a3 = bdec[chunk + 768 + t];

#pragma unroll 4
    for (int j = 0; j < KSP; j++) {
        const float* w = g_WdecT + (size_t)fi[j] * DMODEL + chunk;
        float v = fv[j];
        a0 = fmaf(v, w[t], a0);
        a1 = fmaf(v, w[256 + t], a1);
        a2 = fmaf(v, w[512 + t], a2);
        a3 = fmaf(v, w[768 + t], a3);
    }

    float* o = recon + (size_t)token * DMODEL + chunk;
    o[t]       = a0;
    o[256 + t] = a1;
    o[512 + t] = a2;
    o[768 + t] = a3;
}

// =====================================================================
// launch
// =====================================================================
extern "C" void kernel_launch(void* const* d_in, const int* in_sizes, int n_in,
                              void* d_out, int out_size)
{
    const float* x     = (const float*)d_in[0];
    const float* W_enc = (const float*)d_in[1];
    const float* b_enc = (const float*)d_in[2];
    const float* W_dec = (const float*)d_in[3];
    const float* b_dec = (const float*)d_in[4];

    float* out    = (float*)d_out;
    float* recon  = out;
    float* sparse = out + (size_t)NTOK * DMODEL;
    float* pre    = sparse + (size_t)NTOK * DSAE;

    cudaFuncSetAttribute(topk_select, cudaFuncAttributeMaxDynamicSharedMemorySize,
                         DSAE * (int)sizeof(float));
    cudaFuncSetAttribute(refine, cudaFuncAttributeMaxDynamicSharedMemorySize,
                         DSAE * (int)sizeof(float));
    cudaFuncSetAttribute(enc_imma, cudaFuncAttributeMaxDynamicSharedMemorySize,
                         IB_SMEM);

    int8_t *X1, *X2, *W1, *W2;
    float *sxa, *sxw;
    cudaGetSymbolAddress((void**)&X1,  g_X1);
    cudaGetSymbolAddress((void**)&X2,  g_X2);
    cudaGetSymbolAddress((void**)&W1,  g_W1);
    cudaGetSymbolAddress((void**)&W2,  g_W2);
    cudaGetSymbolAddress((void**)&sxa, g_sxa);
    cudaGetSymbolAddress((void**)&sxw, g_sxw);

    // two-digit int8 quantization of x and W_enc (per-row scales)
    quant_rows<<<NTOK, 256>>>(x,     X1, X2, sxa, DMODEL);
    quant_rows<<<DSAE, 256>>>(W_enc, W1, W2, sxw, DMODEL);

    // IMMA encoder GEMM -> pre_acts (+bias)
    enc_imma<<<(NTOK / IB_BM) * (DSAE / IB_BN), 256, IB_SMEM>>>(b_enc, pre);

    // transpose decoder weights
    wdec_transpose<<<dim3(DSAE / 32, DMODEL / 32), dim3(32, 8)>>>(W_dec);

    // per-token top-64 -> sparse_acts + compacted lists + ambiguity flags
    topk_select<<<NTOK, 256, DSAE * sizeof(float)>>>(pre, sparse);

    // exact fp64 boundary refinement
    refine<<<NTOK, 256, DSAE * sizeof(float)>>>(pre, x, W_enc, sparse);

    // sparse decode -> reconstruction
    sparse_decode<<<dim3(NTOK, DMODEL / 1024), 256>>>(b_dec, recon);
}

// round 15
// speedup vs baseline: 2.6487x; 2.6487x over previous
#include <cuda_runtime.h>
#include <cuda_bf16.h>
#include <cuda_fp16.h>
#include <cstdint>

// Problem constants
#define NTOK   8192
#define DMODEL 4096
#define DSAE   16384
#define KSP    64

// band >= 2x max |pre_computed - pre_true|.
// fp16-single-W path: sigma ~2e-4, R14-measured max ~1.3e-3 over 1.3e8 elems.
// BAND/2 = 3e-3 = ~14 sigma (2.3x measured max) -> guard sound.
#define BAND_EPS 6e-3f
#define BANDCAP 128

// d_out layout: [recon (NTOK*DMODEL) | sparse (NTOK*DSAE) | pre (NTOK*DSAE)]

// ---------------- scratch (__device__ globals) ----------------
__device__ float g_WdecT[(size_t)DSAE * DMODEL];   // 256 MB transposed decoder weights
__device__ int   g_topidx[(size_t)NTOK * KSP];
__device__ float g_topval[(size_t)NTOK * KSP];
__device__ float g_vT[NTOK];
__device__ int   g_flag[NTOK];
// fp16 operands for HMMA encoder (x split into 2 digits; W single fp16)
__device__ __half g_Xhi[(size_t)NTOK * DMODEL];    // 64 MB
__device__ __half g_Xmid[(size_t)NTOK * DMODEL];   // 64 MB
__device__ __half g_Whf[(size_t)DSAE * DMODEL];    // 128 MB

// ---------------- baseline-PTX helpers (sm_80-level only; NO _a features) -----
__device__ __forceinline__ uint32_t smem_to_u32(const void* p) {
    uint32_t a;
    asm("{ .reg .u64 t; cvta.to.shared.u64 t, %1; cvt.u32.u64 %0, t; }"
        : "=r"(a) : "l"(p));
    return a;
}
__device__ __forceinline__ void cp_async16(uint32_t saddr, const void* gaddr) {
    asm volatile("cp.async.cg.shared.global [%0], [%1], 16;" :: "r"(saddr), "l"(gaddr));
}
#define CP_COMMIT() asm volatile("cp.async.commit_group;" ::: "memory")
template <int N>
__device__ __forceinline__ void cp_wait_group() {
    asm volatile("cp.async.wait_group %0;" :: "n"(N) : "memory");
}

// mma.sync m16n8k16 row.col f16 -> f32 (PTX ISA 7.0, baseline sm_80)
__device__ __forceinline__ void mma16816(float* d, const uint32_t* a, const uint32_t* b) {
    asm volatile(
        "mma.sync.aligned.m16n8k16.row.col.f32.f16.f16.f32 "
        "{%0,%1,%2,%3}, {%4,%5,%6,%7}, {%8,%9}, {%0,%1,%2,%3};"
        : "+f"(d[0]), "+f"(d[1]), "+f"(d[2]), "+f"(d[3])
        : "r"(a[0]), "r"(a[1]), "r"(a[2]), "r"(a[3]), "r"(b[0]), "r"(b[1]));
}

// =====================================================================
// Kernel 0a: fp16 two-digit split of x (hi = rn(v), mid = rn(v - hi))
// =====================================================================
__global__ __launch_bounds__(256)
void split_x(const float4* __restrict__ src, uint2* __restrict__ hi,
             uint2* __restrict__ mid, size_t n4)
{
    size_t i = (size_t)blockIdx.x * 256 + threadIdx.x;
    size_t stride = (size_t)gridDim.x * 256;
    for (; i < n4; i += stride) {
        float4 v = src[i];
        __half2 h01 = __floats2half2_rn(v.x, v.y);
        __half2 h23 = __floats2half2_rn(v.z, v.w);
        float2 f01 = __half22float2(h01);
        float2 f23 = __half22float2(h23);
        __half2 m01 = __floats2half2_rn(v.x - f01.x, v.y - f01.y);
        __half2 m23 = __floats2half2_rn(v.z - f23.x, v.w - f23.y);
        hi[i]  = make_uint2(*(uint32_t*)&h01, *(uint32_t*)&h23);
        mid[i] = make_uint2(*(uint32_t*)&m01, *(uint32_t*)&m23);
    }
}

// Kernel 0b: single fp16 conversion of W_enc
__global__ __launch_bounds__(256)
void cvt_w(const float4* __restrict__ src, uint2* __restrict__ dst, size_t n4)
{
    size_t i = (size_t)blockIdx.x * 256 + threadIdx.x;
    size_t stride = (size_t)gridDim.x * 256;
    for (; i < n4; i += stride) {
        float4 v = src[i];
        __half2 h01 = __floats2half2_rn(v.x, v.y);
        __half2 h23 = __floats2half2_rn(v.z, v.w);
        dst[i] = make_uint2(*(uint32_t*)&h01, *(uint32_t*)&h23);
    }
}

// =====================================================================
// Kernel 1: HMMA encoder GEMM (fp16 2-digit x, single-fp16 W):
//   pre = Xhi·Whf^T + Xmid·Whf^T + bias   (fp32 accum)
// CTA tile 128x256, BK=32, 3-stage cp.async pipeline, 256 threads,
// 64x64 warp tiles. 2 MMA passes per k-step (2/3 of bf16x3's count).
// Row stride 80B: conflict-free fragment LDS (bank = 20g+tg).
// =====================================================================
#define HB_BM 128
#define HB_BN 256
#define HB_BK 32
#define HB_RS 80                         // 64B data (32 fp16) + 16B pad
#define HB_A_MAT (128 * HB_RS)           // 10240 B
#define HB_B_MAT (256 * HB_RS)           // 20480 B
#define HB_STAGE (2 * HB_A_MAT + HB_B_MAT)   // 40960 B
#define HB_NSTAGE 3
#define HB_SMEM (HB_NSTAGE * HB_STAGE)   // 122880 B
#define OFF_XHI  0
#define OFF_XMID HB_A_MAT
#define OFF_W    (2 * HB_A_MAT)

__global__ __launch_bounds__(256, 1)
void enc_hmma(const float* __restrict__ bias, float* __restrict__ C)
{
    extern __shared__ char smem[];
    const int tid  = threadIdx.x;
    const int wid  = tid >> 5;
    const int lane = tid & 31;

    // rasterize: groups of 8 M-tiles x all 64 N-tiles
    const int t  = blockIdx.x;
    const int g  = t >> 9;              // /(8*64)
    const int r  = t & 511;
    const int mt = (g << 3) + (r & 7);
    const int nt = r >> 3;
    const int m0 = mt * HB_BM;
    const int n0 = nt * HB_BN;

    const int warp_m = (wid >> 2) * 64;   // 0 / 64
    const int warp_n = (wid & 3) * 64;    // 0..192

    float acc[4][8][4];
#pragma unroll
    for (int i = 0; i < 4; i++)
#pragma unroll
        for (int j = 0; j < 8; j++)
#pragma unroll
            for (int q = 0; q < 4; q++) acc[i][j][q] = 0.0f;

    const uint32_t sb = smem_to_u32(smem);
    const int NCH = DMODEL / HB_BK;      // 128

    // ---- per-thread loader plan: 8 x 16B chunks per stage (2048 total) ----
    uint32_t soff[8];
    const char* gptr[8];
    {
        const char* gXhi  = (const char*)g_Xhi  + (size_t)m0 * DMODEL * 2;
        const char* gXmid = (const char*)g_Xmid + (size_t)m0 * DMODEL * 2;
        const char* gW    = (const char*)g_Whf  + (size_t)n0 * DMODEL * 2;
#pragma unroll
        for (int i = 0; i < 8; i++) {
            int c = tid + i * 256;
            if (c < 512) {                        // Xhi: 128 rows x 4 chunks
                int row = c >> 2, c16 = c & 3;
                soff[i] = OFF_XHI + row * HB_RS + c16 * 16;
                gptr[i] = gXhi + (size_t)row * (DMODEL * 2) + c16 * 16;
            } else if (c < 1024) {                // Xmid
                int cb = c - 512;
                int row = cb >> 2, c16 = cb & 3;
                soff[i] = OFF_XMID + row * HB_RS + c16 * 16;
                gptr[i] = gXmid + (size_t)row * (DMODEL * 2) + c16 * 16;
            } else {                              // W: 256 rows x 4 chunks
                int cb = c - 1024;
                int row = cb >> 2, c16 = cb & 3;
                soff[i] = OFF_W + row * HB_RS + c16 * 16;
                gptr[i] = gW + (size_t)row * (DMODEL * 2) + c16 * 16;
            }
        }
    }

    auto load_stage = [&](int ch, int s) {
        const uint32_t stg = sb + s * HB_STAGE;
        const size_t kadv = (size_t)ch * 64;     // 32 fp16 = 64 bytes per chunk
#pragma unroll
        for (int i = 0; i < 8; i++)
            cp_async16(stg + soff[i], gptr[i] + kadv);
        CP_COMMIT();
    };

    load_stage(0, 0);
    load_stage(1, 1);

    const int gg = lane >> 2;
    const int tg = lane & 3;

    for (int ch = 0; ch < NCH; ch++) {
        if (ch + 1 < NCH) cp_wait_group<1>();
        else              cp_wait_group<0>();
        __syncthreads();

        if (ch + 2 < NCH) load_stage(ch + 2, (ch + 2) % 3);

        const char* stg = smem + (ch % 3) * HB_STAGE;

#pragma unroll
        for (int ks = 0; ks < 2; ks++) {
            const int kb = ks * 32;              // 16 fp16 = 32B per k-step
            uint32_t ah[4][4], am[4][4], bw[8][2];
#pragma unroll
            for (int i = 0; i < 4; i++) {
                const char* pa = stg + OFF_XHI +
                                 (warp_m + i * 16 + gg) * HB_RS + kb + tg * 4;
                ah[i][0] = *(const uint32_t*)pa;
                ah[i][1] = *(const uint32_t*)(pa + 8 * HB_RS);
                ah[i][2] = *(const uint32_t*)(pa + 16);
                ah[i][3] = *(const uint32_t*)(pa + 8 * HB_RS + 16);
                const char* pm = pa + (OFF_XMID - OFF_XHI);
                am[i][0] = *(const uint32_t*)pm;
                am[i][1] = *(const uint32_t*)(pm + 8 * HB_RS);
                am[i][2] = *(const uint32_t*)(pm + 16);
                am[i][3] = *(const uint32_t*)(pm + 8 * HB_RS + 16);
            }
#pragma unroll
            for (int j = 0; j < 8; j++) {
                const char* pb = stg + OFF_W +
                                 (warp_n + j * 8 + gg) * HB_RS + kb + tg * 4;
                bw[j][0] = *(const uint32_t*)pb;
                bw[j][1] = *(const uint32_t*)(pb + 16);
            }
            // pass 1: hi * W  (32 independent MMAs)
#pragma unroll
            for (int j = 0; j < 8; j++)
#pragma unroll
                for (int i = 0; i < 4; i++)
                    mma16816(acc[i][j], ah[i], bw[j]);
            // pass 2: mid * W
#pragma unroll
            for (int j = 0; j < 8; j++)
#pragma unroll
                for (int i = 0; i < 4; i++)
                    mma16816(acc[i][j], am[i], bw[j]);
        }
    }

    // ---- epilogue: bias add + store ----
#pragma unroll
    for (int i = 0; i < 4; i++) {
        const int row0 = m0 + warp_m + i * 16 + gg;
#pragma unroll
        for (int j = 0; j < 8; j++) {
            const int col = n0 + warp_n + j * 8 + tg * 2;
            const float b0 = bias[col];
            const float b1 = bias[col + 1];
            float* p0 = C + (size_t)row0 * DSAE + col;
            float* p1 = C + (size_t)(row0 + 8) * DSAE + col;
            *(float2*)p0 = make_float2(acc[i][j][0] + b0, acc[i][j][1] + b1);
            *(float2*)p1 = make_float2(acc[i][j][2] + b0, acc[i][j][3] + b1);
        }
    }
}

// =====================================================================
// Kernel 2: transpose W_dec (DMODEL x DSAE) -> g_WdecT (DSAE x DMODEL)
// =====================================================================
__global__ __launch_bounds__(256)
void wdec_transpose(const float* __restrict__ W)
{
    __shared__ float s[32][33];
    const int f0 = blockIdx.x * 32;
    const int d0 = blockIdx.y * 32;
    const int tx = threadIdx.x;
    const int ty = threadIdx.y;
#pragma unroll
    for (int j = 0; j < 32; j += 8)
        s[ty + j][tx] = W[(size_t)(d0 + ty + j) * DSAE + f0 + tx];
    __syncthreads();
#pragma unroll
    for (int j = 0; j < 32; j += 8)
        g_WdecT[(size_t)(f0 + ty + j) * DMODEL + d0 + tx] = s[tx][ty + j];
}

// =====================================================================
// Kernel 3: per-token top-64 radix select + ambiguity flagging
// =====================================================================
__device__ __forceinline__ unsigned int fkey(float x) {
    unsigned int u = __float_as_uint(x);
    unsigned int m = ((unsigned int)((int)u >> 31)) | 0x80000000u;
    return u ^ m;
}
__device__ __forceinline__ float keyval(unsigned int k) {
    unsigned int u = (k & 0x80000000u) ? (k ^ 0x80000000u) : ~k;
    return __uint_as_float(u);
}

__global__ __launch_bounds__(256)
void topk_select(const float* __restrict__ pre, float* __restrict__ sparse)
{
    extern __shared__ float srow[];
    __shared__ unsigned int hist[8][256];
    __shared__ unsigned int bitmap[DSAE / 32];
    __shared__ int s_gt[256], s_eq[256], s_base[256], s_ebase[256];
    __shared__ unsigned int sh_pfx;
    __shared__ int sh_need;
    __shared__ int s_flag;

    const int token = blockIdx.x;
    const int tid = threadIdx.x;
    const int wid = tid >> 5;
    const float* prow = pre + (size_t)token * DSAE;

    for (int i = tid; i < DSAE; i += 256) srow[i] = prow[i];
    __syncthreads();

    unsigned int pfx = 0;
    int need = KSP;
    for (int b = 3; b >= 0; --b) {
        for (int i = tid; i < 8 * 256; i += 256) ((unsigned int*)hist)[i] = 0;
        __syncthreads();
        const int sh = b * 8;
        for (int i = tid; i < DSAE; i += 256) {
            unsigned int k = fkey(srow[i]);
            bool m = (b == 3) || ((k >> (sh + 8)) == pfx);
            if (m) atomicAdd(&hist[wid][(k >> sh) & 255], 1u);
        }
        __syncthreads();
        if (tid < 256) {
            unsigned int s = 0;
#pragma unroll
            for (int w = 0; w < 8; w++) s += hist[w][tid];
            hist[0][tid] = s;
        }
        __syncthreads();
        if (tid == 0) {
            int cum = 0, v = 255;
            for (; v > 0; --v) {
                int c = (int)hist[0][v];
                if (cum + c >= need) break;
                cum += c;
            }
            sh_pfx = (pfx << 8) | (unsigned int)v;
            sh_need = need - cum;
        }
        __syncthreads();
        pfx = sh_pfx;
        need = sh_need;
        __syncthreads();
    }
    const unsigned int T = pfx;
    const int r = need;
    const float vT = keyval(T);

    const int seg = tid * 64;
    {
        int ngt = 0, neq = 0;
#pragma unroll 4
        for (int ii = 0; ii < 64; ii++) {
            unsigned int k = fkey(srow[seg + ii]);
            ngt += (k > T);
            neq += (k == T);
        }
        s_gt[tid] = ngt;
        s_eq[tid] = neq;
    }
    if (tid == 0) s_flag = 0;
    __syncthreads();
    if (tid == 0) {
        int eacc = 0, sacc = 0;
        for (int q = 0; q < 256; q++) {
            s_ebase[q] = eacc;
            int etake = r - eacc;
            if (etake < 0) etake = 0;
            if (etake > s_eq[q]) etake = s_eq[q];
            s_base[q] = sacc;
            sacc += s_gt[q] + etake;
            eacc += s_eq[q];
        }
    }
    __syncthreads();

    {
        unsigned int bits0 = 0, bits1 = 0;
        int p = s_base[tid];
        int e = s_ebase[tid];
        int*   oidx = g_topidx + (size_t)token * KSP;
        float* oval = g_topval + (size_t)token * KSP;
        for (int ii = 0; ii < 64; ii++) {
            int i = seg + ii;
            float x = srow[i];
            unsigned int k = fkey(x);
            bool gt = (k > T);
            bool eq = (k == T);
            bool take = gt || (eq && e < r);
            if (eq) e++;
            if (take) {
                oidx[p] = i;
                oval[p] = x;
                if (ii < 32) bits0 |= (1u << ii);
                else         bits1 |= (1u << (ii - 32));
                p++;
            }
        }
        bitmap[tid * 2]     = bits0;
        bitmap[tid * 2 + 1] = bits1;
    }
    __syncthreads();

    float* srow_out = sparse + (size_t)token * DSAE;
    for (int i = tid; i < DSAE; i += 256) {
        bool sel = (bitmap[i >> 5] >> (i & 31)) & 1u;
        float v = srow[i];
        srow_out[i] = sel ? v : 0.0f;
        if (!sel && fabsf(v - vT) <= BAND_EPS) s_flag = 1;
    }
    __syncthreads();
    if (tid == 0) {
        g_vT[token] = vT;
        g_flag[token] = s_flag;
    }
}

// =====================================================================
// Kernel 3b: exact fp64 boundary refinement (warp-parallel candidate dots;
// flag rate ~95% on the wide band, so this path must be fast)
// =====================================================================
__global__ __launch_bounds__(256)
void refine(const float* __restrict__ pre,
            const float* __restrict__ x,
            const float* __restrict__ Wenc,
            float* __restrict__ sparse)
{
    extern __shared__ float srow[];
    __shared__ int    s_band[BANDCAP];
    __shared__ float  s_ef[BANDCAP];
    __shared__ unsigned int bm[DSAE / 32];
    __shared__ int s_cnt[256], s_base[256];
    __shared__ int s_chosen[64];
    __shared__ int s_nin, s_c, s_nch;

    const int token = blockIdx.x;
    if (!g_flag[token]) return;

    const int tid  = threadIdx.x;
    const int wid  = tid >> 5;
    const int lane = tid & 31;
    const float vT = g_vT[token];
    const float* prow = pre + (size_t)token * DSAE;

    for (int i = tid; i < DSAE; i += 256) srow[i] = prow[i];
    if (tid == 0) { s_nin = 0; s_c = 0; }
    __syncthreads();

    int nin_local = 0;
    for (int i = tid; i < DSAE; i += 256) {
        float v = srow[i];
        if (v > vT + BAND_EPS) {
            nin_local++;
        } else if (fabsf(v - vT) <= BAND_EPS) {
            int p = atomicAdd(&s_c, 1);
            if (p < BANDCAP) s_band[p] = i;
        }
    }
    atomicAdd(&s_nin, nin_local);
    __syncthreads();

    const int c = min(s_c, BANDCAP);
    const int need = KSP - s_nin;

    if (tid == 0) {
        for (int a = 1; a < c; a++) {
            int key = s_band[a], b = a - 1;
            for (; b >= 0 && s_band[b] > key; b--) s_band[b + 1] = s_band[b];
            s_band[b + 1] = key;
        }
    }
    __syncthreads();

    // warp-parallel exact fp64 dots (one candidate per warp)
    const float* xr = x + (size_t)token * DMODEL;
    for (int j0 = 0; j0 < c; j0 += 8) {
        int j = j0 + wid;
        if (j < c) {
            const float* wr = Wenc + (size_t)s_band[j] * DMODEL;
            double p = 0.0;
            for (int d = lane; d < DMODEL; d += 32)
                p += (double)xr[d] * (double)wr[d];
#pragma unroll
            for (int o = 16; o > 0; o >>= 1)
                p += __shfl_down_sync(0xFFFFFFFFu, p, o);
            if (lane == 0) s_ef[j] = (float)p;
        }
    }
    __syncthreads();

    if (tid == 0) {
        bool used[BANDCAP];
        for (int j = 0; j < c; j++) used[j] = false;
        int nc = 0;
        for (int t = 0; t < need && t < c; t++) {
            int best = -1;
            for (int j = 0; j < c; j++)
                if (!used[j] && (best < 0 || s_ef[j] > s_ef[best])) best = j;
            used[best] = true;
            s_chosen[nc++] = s_band[best];
        }
        s_nch = nc;
    }
    __syncthreads();

    {
        int seg = tid * 64;
        unsigned int b0 = 0, b1 = 0;
        for (int ii = 0; ii < 64; ii++) {
            float v = srow[seg + ii];
            if (v > vT + BAND_EPS) {
                if (ii < 32) b0 |= (1u << ii);
                else         b1 |= (1u << (ii - 32));
            }
        }
        bm[tid * 2]     = b0;
        bm[tid * 2 + 1] = b1;
    }
    __syncthreads();
    if (tid == 0)
        for (int t = 0; t < s_nch; t++) {
            int i = s_chosen[t];
            bm[i >> 5] |= (1u << (i & 31));
        }
    __syncthreads();

    s_cnt[tid] = __popc(bm[tid * 2]) + __popc(bm[tid * 2 + 1]);
    __syncthreads();
    if (tid == 0) {
        int acc = 0;
        for (int q = 0; q < 256; q++) { s_base[q] = acc; acc += s_cnt[q]; }
    }
    __syncthreads();

    float* srow_out = sparse + (size_t)token * DSAE;
    int*   oidx = g_topidx + (size_t)token * KSP;
    float* oval = g_topval + (size_t)token * KSP;
    {
        int seg = tid * 64;
        int p = s_base[tid];
        for (int ii = 0; ii < 64; ii++) {
            int i = seg + ii;
            bool sel = (bm[i >> 5] >> (i & 31)) & 1u;
            srow_out[i] = sel ? srow[i] : 0.0f;
            if (sel) { oidx[p] = i; oval[p] = srow[i]; p++; }
        }
    }
}

// =====================================================================
// Kernel 4: sparse decoder
// =====================================================================
__global__ __launch_bounds__(256)
void sparse_decode(const float* __restrict__ bdec,
                   float* __restrict__ recon)
{
    const int token = blockIdx.x;
    const int chunk = blockIdx.y * 1024;
    const int t = threadIdx.x;

    __shared__ int   fi[KSP];
    __shared__ float fv[KSP];
    if (t < KSP) {
        fi[t] = g_topidx[(size_t)token * KSP + t];
        fv[t] = g_topval[(size_t)token * KSP + t];
    }
    __syncthreads();

    float a0 = bdec[chunk + t];
    float a1 = bdec[chunk + 256 + t];
    float a2 = bdec[chunk + 512 + t];
    float a3 = bdec[chunk + 768 + t];

#pragma unroll 4
    for (int j = 0; j < KSP; j++) {
        const float* w = g_WdecT + (size_t)fi[j] * DMODEL + chunk;
        float v = fv[j];
        a0 = fmaf(v, w[t], a0);
        a1 = fmaf(v, w[256 + t], a1);
        a2 = fmaf(v, w[512 + t], a2);
        a3 = fmaf(v, w[768 + t], a3);
    }

    float* o = recon + (size_t)token * DMODEL + chunk;
    o[t]       = a0;
    o[256 + t] = a1;
    o[512 + t] = a2;
    o[768 + t] = a3;
}

// =====================================================================
// launch
// =====================================================================
extern "C" void kernel_launch(void* const* d_in, const int* in_sizes, int n_in,
                              void* d_out, int out_size)
{
    const float* x     = (const float*)d_in[0];
    const float* W_enc = (const float*)d_in[1];
    const float* b_enc = (const float*)d_in[2];
    const float* W_dec = (const float*)d_in[3];
    const float* b_dec = (const float*)d_in[4];

    float* out    = (float*)d_out;
    float* recon  = out;
    float* sparse = out + (size_t)NTOK * DMODEL;
    float* pre    = sparse + (size_t)NTOK * DSAE;

    cudaFuncSetAttribute(topk_select, cudaFuncAttributeMaxDynamicSharedMemorySize,
                         DSAE * (int)sizeof(float));
    cudaFuncSetAttribute(refine, cudaFuncAttributeMaxDynamicSharedMemorySize,
                         DSAE * (int)sizeof(float));
    cudaFuncSetAttribute(enc_hmma, cudaFuncAttributeMaxDynamicSharedMemorySize,
                         HB_SMEM);

    __half *Xhi, *Xmid, *Whf;
    cudaGetSymbolAddress((void**)&Xhi,  g_Xhi);
    cudaGetSymbolAddress((void**)&Xmid, g_Xmid);
    cudaGetSymbolAddress((void**)&Whf,  g_Whf);

    // fp16 splits: x -> hi+mid digits; W_enc -> single fp16
    split_x<<<2048, 256>>>((const float4*)x, (uint2*)Xhi, (uint2*)Xmid,
                           (size_t)NTOK * DMODEL / 4);
    cvt_w<<<4096, 256>>>((const float4*)W_enc, (uint2*)Whf,
                         (size_t)DSAE * DMODEL / 4);

    // HMMA encoder GEMM -> pre_acts (+bias), 2 MMA passes per k-step
    enc_hmma<<<(NTOK / HB_BM) * (DSAE / HB_BN), 256, HB_SMEM>>>(b_enc, pre);

    // transpose decoder weights
    wdec_transpose<<<dim3(DSAE / 32, DMODEL / 32), dim3(32, 8)>>>(W_dec);

    // per-token top-64 -> sparse_acts + compacted lists + ambiguity flags
    topk_select<<<NTOK, 256, DSAE * sizeof(float)>>>(pre, sparse);

    // exact fp64 boundary refinement (warp-parallel dots)
    refine<<<NTOK, 256, DSAE * sizeof(float)>>>(pre, x, W_enc, sparse);

    // sparse decode -> reconstruction
    sparse_decode<<<dim3(NTOK, DMODEL / 1024), 256>>>(b_dec, recon);
}